// round 3
// baseline (speedup 1.0000x reference)
#include <cuda_runtime.h>
#include <cstdint>

static constexpr int       kNumPos = 8192;
static constexpr long long kNTot   = 32776192LL;            // 8192 + 8192*4000
static constexpr long long kMagicM = 34359739LL;            // ceil(2^37/4000)
static constexpr long long kMagicB = -281474981888LL;       // -8192*M
static constexpr int       kShift  = 37;

// Count-kernel geometry: one wave of 152 CTAs, 8 warps each.
static constexpr int NBLK_B = 152;
static constexpr int THR_B  = 256;
static constexpr int NWARP_B = 8;
static constexpr int SMEM_B = kNumPos * 4 + NWARP_B * kNumPos * 2;  // 160 KB

static constexpr int NBLK_A = 608;   // scatter kernel blocks

__device__ float    g_pos[kNumPos];
__device__ unsigned g_partial[NBLK_B * kNumPos];
__device__ int      g_is64;

// ---------------------------------------------------------------------------
__global__ void detect_kernel(const unsigned long long* __restrict__ idx) {
    if (threadIdx.x == 0 && blockIdx.x == 0) {
        int is64 = 1;
        #pragma unroll
        for (int i = 0; i < 64; ++i)
            if (idx[i] >= (unsigned long long)kNTot) is64 = 0;
        g_is64 = is64;
    }
}

// ---------------------------------------------------------------------------
// Pass A: scan index, scatter pos values (rare). Batched loads for MLP.
// ---------------------------------------------------------------------------
__global__ void __launch_bounds__(256) scatter_pos_kernel(
    const void* __restrict__ idx_raw, const float* __restrict__ pred,
    float* __restrict__ out) {
    if (blockIdx.x == 0 && threadIdx.x == 0) out[0] = 0.0f;
    const long long base   = blockIdx.x * 256LL + threadIdx.x;
    const long long stride = (long long)NBLK_A * 256LL;
    constexpr int U = 8;
    const long long bigstride = stride * U;

    if (g_is64) {
        const uint4* idx4 = (const uint4*)idx_raw;     // 1 uint4 = 2 int64 elems
        const long long nvec = kNTot / 2;
        const long long nmax = nvec - 1;
        const int iters = (int)((nvec + bigstride - 1) / bigstride);
        for (int it = 0; it < iters; ++it) {
            uint4 iv[U];
            long long vs[U];
            #pragma unroll
            for (int u = 0; u < U; ++u) {
                long long v = base + (long long)it * bigstride + (long long)u * stride;
                vs[u] = v;
                iv[u] = idx4[v > nmax ? nmax : v];
            }
            #pragma unroll
            for (int u = 0; u < U; ++u) {
                if (vs[u] < nvec) {
                    const long long e = 2 * vs[u];
                    if (iv[u].x < (unsigned)kNumPos) g_pos[iv[u].x] = pred[e];
                    if (iv[u].z < (unsigned)kNumPos) g_pos[iv[u].z] = pred[e + 1];
                }
            }
        }
    } else {
        const uint4* idx4 = (const uint4*)idx_raw;     // 1 uint4 = 4 int32 elems
        const long long nvec = kNTot / 4;
        const long long nmax = nvec - 1;
        const int iters = (int)((nvec + bigstride - 1) / bigstride);
        for (int it = 0; it < iters; ++it) {
            uint4 iv[U];
            long long vs[U];
            #pragma unroll
            for (int u = 0; u < U; ++u) {
                long long v = base + (long long)it * bigstride + (long long)u * stride;
                vs[u] = v;
                iv[u] = idx4[v > nmax ? nmax : v];
            }
            #pragma unroll
            for (int u = 0; u < U; ++u) {
                if (vs[u] < nvec) {
                    const long long e = 4 * vs[u];
                    if (iv[u].x < (unsigned)kNumPos) g_pos[iv[u].x] = pred[e];
                    if (iv[u].y < (unsigned)kNumPos) g_pos[iv[u].y] = pred[e + 1];
                    if (iv[u].z < (unsigned)kNumPos) g_pos[iv[u].z] = pred[e + 2];
                    if (iv[u].w < (unsigned)kNumPos) g_pos[iv[u].w] = pred[e + 3];
                }
            }
        }
    }
}

// ---------------------------------------------------------------------------
// Pass B: per-warp u16 smem histograms, match-based leader aggregation.
// Double-buffered register pipeline keeps LDGs in flight during processing.
// ---------------------------------------------------------------------------
__device__ __forceinline__ void hist_step(unsigned i, float val, bool inb, int lane,
                                          unsigned mlt,
                                          const float* __restrict__ s_pos,
                                          unsigned short* __restrict__ myhist) {
    // s = (i - 8192) / 4000 via exact magic divide (valid for i < 2^25).
    const unsigned s  = (unsigned)(((long long)i * kMagicM + kMagicB) >> kShift);
    const unsigned sm = s & 8191u;
    const float    p  = s_pos[sm];                  // always-safe address
    const bool bit = inb && (s < 8192u) && (val > p);
    const unsigned key = bit ? sm : 8192u + (unsigned)lane;
    const unsigned grp = __match_any_sync(0xffffffffu, key);
    if (bit && (grp & mlt) == 0u) {                 // leader = lowest lane in group
        myhist[sm] = (unsigned short)(myhist[sm] + (unsigned)__popc(grp));
    }
}

// Batch containers: one "unit" = 4 elements.
struct Batch32 { uint4 iv[4]; float4 vv[4]; };
struct Batch64 { uint4 iv[8]; float4 vv[4]; };   // 2 uint4 per unit (lo words at .x/.z)

__global__ void __launch_bounds__(THR_B, 1) count_kernel(
    const void* __restrict__ idx_raw, const float* __restrict__ pred) {
    extern __shared__ unsigned char smem_raw[];
    float*          s_pos  = (float*)smem_raw;
    unsigned short* s_hist = (unsigned short*)(smem_raw + (size_t)kNumPos * 4);
    const int tid  = threadIdx.x;
    const int lane = tid & 31;
    unsigned mlt;
    asm("mov.u32 %0, %%lanemask_lt;" : "=r"(mlt));
    unsigned short* myhist = s_hist + (size_t)(tid >> 5) * kNumPos;

    for (int k = tid; k < kNumPos; k += THR_B) s_pos[k] = g_pos[k];
    unsigned* s_hist32 = (unsigned*)s_hist;
    for (int k = tid; k < NWARP_B * kNumPos / 2; k += THR_B) s_hist32[k] = 0u;
    __syncthreads();

    constexpr int U = 4;                                  // units per batch (16 elems)
    const long long n_units   = kNTot / 4;                // 8,194,048
    const long long nmax      = n_units - 1;
    const long long stride    = (long long)NBLK_B * THR_B;
    const long long bigstride = stride * U;
    const long long base      = blockIdx.x * (long long)THR_B + tid;
    const int iters = (int)((n_units + bigstride - 1) / bigstride);  // 53, uniform

    if (g_is64) {
        const uint4*  idx4 = (const uint4*)idx_raw;
        const float4* val4 = (const float4*)pred;
        auto load = [&](int it, Batch64& b) {
            #pragma unroll
            for (int u = 0; u < U; ++u) {
                long long v = base + (long long)it * bigstride + (long long)u * stride;
                long long vc = v > nmax ? nmax : v;
                b.iv[2 * u]     = idx4[2 * vc];
                b.iv[2 * u + 1] = idx4[2 * vc + 1];
                b.vv[u]         = val4[vc];
            }
        };
        auto process = [&](int it, const Batch64& b) {
            #pragma unroll
            for (int u = 0; u < U; ++u) {
                long long v = base + (long long)it * bigstride + (long long)u * stride;
                const bool inb = (v < n_units);
                hist_step(b.iv[2*u].x,   b.vv[u].x, inb, lane, mlt, s_pos, myhist);
                hist_step(b.iv[2*u].z,   b.vv[u].y, inb, lane, mlt, s_pos, myhist);
                hist_step(b.iv[2*u+1].x, b.vv[u].z, inb, lane, mlt, s_pos, myhist);
                hist_step(b.iv[2*u+1].z, b.vv[u].w, inb, lane, mlt, s_pos, myhist);
            }
        };
        Batch64 A, B;
        load(0, A);
        #pragma unroll 1
        for (int it = 0; it < iters; ) {
            load(it + 1, B);          // harmless clamped prefetch past the end
            process(it, A);
            if (++it >= iters) break;
            load(it + 1, A);
            process(it, B);
            if (++it >= iters) break;
        }
    } else {
        const uint4*  idx4 = (const uint4*)idx_raw;
        const float4* val4 = (const float4*)pred;
        auto load = [&](int it, Batch32& b) {
            #pragma unroll
            for (int u = 0; u < U; ++u) {
                long long v = base + (long long)it * bigstride + (long long)u * stride;
                long long vc = v > nmax ? nmax : v;
                b.iv[u] = idx4[vc];
                b.vv[u] = val4[vc];
            }
        };
        auto process = [&](int it, const Batch32& b) {
            #pragma unroll
            for (int u = 0; u < U; ++u) {
                long long v = base + (long long)it * bigstride + (long long)u * stride;
                const bool inb = (v < n_units);
                hist_step(b.iv[u].x, b.vv[u].x, inb, lane, mlt, s_pos, myhist);
                hist_step(b.iv[u].y, b.vv[u].y, inb, lane, mlt, s_pos, myhist);
                hist_step(b.iv[u].z, b.vv[u].z, inb, lane, mlt, s_pos, myhist);
                hist_step(b.iv[u].w, b.vv[u].w, inb, lane, mlt, s_pos, myhist);
            }
        };
        Batch32 A, B;
        load(0, A);
        #pragma unroll 1
        for (int it = 0; it < iters; ) {
            load(it + 1, B);
            process(it, A);
            if (++it >= iters) break;
            load(it + 1, A);
            process(it, B);
            if (++it >= iters) break;
        }
    }
    __syncthreads();

    // Combine 8 warp histograms; one u32 partial per bin per block.
    for (int k = tid; k < kNumPos; k += THR_B) {
        unsigned c = 0;
        #pragma unroll
        for (int w = 0; w < NWARP_B; ++w) c += s_hist[(size_t)w * kNumPos + k];
        g_partial[(size_t)blockIdx.x * kNumPos + k] = c;
    }
}

// ---------------------------------------------------------------------------
// Pass C: 256 blocks x 256 threads. out layout: [mrr, sample_mrr[8192]]
// ---------------------------------------------------------------------------
__global__ void __launch_bounds__(256) finalize_kernel(float* __restrict__ out) {
    const int tid   = threadIdx.x;
    const int bsub  = tid & 31;
    const int chunk = tid >> 5;
    const int bin   = blockIdx.x * 32 + bsub;

    unsigned c = 0;
    #pragma unroll
    for (int b = chunk; b < NBLK_B; b += 8)
        c += g_partial[(size_t)b * kNumPos + bin];

    __shared__ unsigned sc[256];
    sc[tid] = c;
    __syncthreads();

    if (chunk == 0) {
        unsigned tot = c;
        #pragma unroll
        for (int w = 1; w < 8; ++w) tot += sc[w * 32 + bsub];
        const float mrr_i = 1.0f / (float)(1u + tot);
        out[1 + bin] = mrr_i;

        float s = mrr_i;
        #pragma unroll
        for (int o = 16; o; o >>= 1) s += __shfl_down_sync(0xffffffffu, s, o);
        if (bsub == 0) atomicAdd(out, s * (1.0f / (float)kNumPos));
    }
}

// ---------------------------------------------------------------------------
extern "C" void kernel_launch(void* const* d_in, const int* in_sizes, int n_in,
                              void* d_out, int out_size) {
    const float* pred = (const float*)d_in[0];
    const void*  idx  = (const void*)d_in[1];
    float*       out  = (float*)d_out;

    cudaFuncSetAttribute(count_kernel, cudaFuncAttributeMaxDynamicSharedMemorySize, SMEM_B);

    detect_kernel<<<1, 32>>>((const unsigned long long*)idx);
    scatter_pos_kernel<<<NBLK_A, 256>>>(idx, pred, out);
    count_kernel<<<NBLK_B, THR_B, SMEM_B>>>(idx, pred);
    finalize_kernel<<<kNumPos / 32, 256>>>(out);
}

// round 4
// speedup vs baseline: 1.2849x; 1.2849x over previous
#include <cuda_runtime.h>
#include <cstdint>

static constexpr int       kNumPos = 8192;
static constexpr long long kNTot   = 32776192LL;            // 8192 + 8192*4000
static constexpr long long kMagicM = 34359739LL;            // ceil(2^37/4000)
static constexpr long long kMagicB = -281474981888LL;       // -8192*M
static constexpr int       kShift  = 37;

static constexpr int NBLK_B  = 152;
static constexpr int THR_B   = 256;
static constexpr int NWARP_B = 8;

// cp.async pipeline geometry
static constexpr int TILE   = 1024;                         // elements per tile
static constexpr int NTILES = (int)(kNTot / TILE);          // 32008, exact
static constexpr int NS     = 4;                            // stages (power of 2)
static constexpr int OFF_POS   = 0;
static constexpr int OFF_HIST  = kNumPos * 4;                           // 32 KB
static constexpr int OFF_STAGE = OFF_HIST + NWARP_B * kNumPos * 2;      // 160 KB
static constexpr int STAGE_STRIDE = TILE * 8 + TILE * 4;                // 12 KB
static constexpr int SMEM_B  = OFF_STAGE + NS * STAGE_STRIDE;           // 208 KB

__device__ float    g_pos[kNumPos];
__device__ unsigned g_partial[NBLK_B * kNumPos];
__device__ int      g_is64;

// ---------------------------------------------------------------------------
__global__ void detect_kernel(const unsigned long long* __restrict__ idx) {
    if (threadIdx.x == 0 && blockIdx.x == 0) {
        int is64 = 1;
        #pragma unroll
        for (int i = 0; i < 64; ++i)
            if (idx[i] >= (unsigned long long)kNTot) is64 = 0;
        g_is64 = is64;
    }
}

// ---------------------------------------------------------------------------
// Pass A: scan index, scatter pos values. (Round-2 version, known good.)
// ---------------------------------------------------------------------------
__global__ void __launch_bounds__(256) scatter_pos_kernel(
    const void* __restrict__ idx_raw, const float* __restrict__ pred,
    float* __restrict__ out) {
    if (blockIdx.x == 0 && threadIdx.x == 0) out[0] = 0.0f;
    const long long tid    = blockIdx.x * (long long)blockDim.x + threadIdx.x;
    const long long stride = (long long)gridDim.x * blockDim.x;
    if (g_is64) {
        const ulonglong2* idx2 = (const ulonglong2*)idx_raw;
        const long long nvec = kNTot / 2;
        #pragma unroll 4
        for (long long v = tid; v < nvec; v += stride) {
            ulonglong2 iv = idx2[v];
            if (iv.x < (unsigned long long)kNumPos) g_pos[iv.x] = pred[2 * v];
            if (iv.y < (unsigned long long)kNumPos) g_pos[iv.y] = pred[2 * v + 1];
        }
    } else {
        const uint4* idx4 = (const uint4*)idx_raw;
        const long long nvec = kNTot / 4;
        #pragma unroll 4
        for (long long v = tid; v < nvec; v += stride) {
            uint4 iv = idx4[v];
            if (iv.x < (unsigned)kNumPos) g_pos[iv.x] = pred[4 * v];
            if (iv.y < (unsigned)kNumPos) g_pos[iv.y] = pred[4 * v + 1];
            if (iv.z < (unsigned)kNumPos) g_pos[iv.z] = pred[4 * v + 2];
            if (iv.w < (unsigned)kNumPos) g_pos[iv.w] = pred[4 * v + 3];
        }
    }
}

// ---------------------------------------------------------------------------
// Pass B: cp.async-staged tiles -> per-warp u16 smem histograms.
// ---------------------------------------------------------------------------
__device__ __forceinline__ void cp16(uint32_t s, const void* g) {
    asm volatile("cp.async.cg.shared.global [%0], [%1], 16;\n" :: "r"(s), "l"(g));
}

__device__ __forceinline__ void hist_step(unsigned i, float val, int lane,
                                          unsigned mlt,
                                          const float* __restrict__ s_pos,
                                          unsigned short* __restrict__ myhist) {
    // s = (i - 8192) / 4000, exact magic divide; pos elements (i<8192) wrap to
    // huge s -> bit false; sm is masked so the LDS address is always safe.
    const unsigned s  = (unsigned)(((long long)i * kMagicM + kMagicB) >> kShift);
    const unsigned sm = s & 8191u;
    const float    p  = s_pos[sm];
    const bool bit = (s < 8192u) && (val > p);
    const unsigned key = bit ? sm : 8192u + (unsigned)lane;
    const unsigned grp = __match_any_sync(0xffffffffu, key);
    if (bit && (grp & mlt) == 0u) {                  // leader = lowest lane in group
        myhist[sm] = (unsigned short)(myhist[sm] + (unsigned)__popc(grp));
    }
}

__global__ void __launch_bounds__(THR_B, 1) count_kernel(
    const void* __restrict__ idx_raw, const float* __restrict__ pred) {
    extern __shared__ char smem[];
    float*          s_pos  = (float*)(smem + OFF_POS);
    unsigned short* s_hist = (unsigned short*)(smem + OFF_HIST);
    const int tid  = threadIdx.x;
    const int lane = tid & 31;
    unsigned mlt;
    asm("mov.u32 %0, %%lanemask_lt;" : "=r"(mlt));
    unsigned short* myhist = s_hist + (size_t)(tid >> 5) * kNumPos;

    for (int k = tid; k < kNumPos; k += THR_B) s_pos[k] = g_pos[k];
    unsigned* h32 = (unsigned*)s_hist;
    for (int k = tid; k < NWARP_B * kNumPos / 2; k += THR_B) h32[k] = 0u;
    __syncthreads();

    const int  is64 = g_is64;
    const char* gidx = (const char*)idx_raw;
    const uint32_t stage_base = (uint32_t)__cvta_generic_to_shared(smem + OFF_STAGE);

    auto issue = [&](int k) {
        const long long t = (long long)blockIdx.x + (long long)k * NBLK_B;
        if (t < NTILES) {
            const uint32_t sb = stage_base + (((unsigned)k) & (NS - 1)) * STAGE_STRIDE;
            const float* gv = pred + t * (long long)TILE;
            if (is64) {
                const char* gi = gidx + t * (long long)TILE * 8;
                cp16(sb + tid * 16,         gi + tid * 16);
                cp16(sb + (tid + 256) * 16, gi + (tid + 256) * 16);
            } else {
                const char* gi = gidx + t * (long long)TILE * 4;
                cp16(sb + tid * 16, gi + tid * 16);
            }
            cp16(sb + TILE * 8 + tid * 16, (const char*)gv + tid * 16);
        }
        asm volatile("cp.async.commit_group;");
    };

    // Prologue: NS-1 tiles in flight.
    issue(0); issue(1); issue(2);

    const int wbase = (tid >> 5) * 128 + lane;
    #pragma unroll 1
    for (int k = 0;; ++k) {
        const long long t = (long long)blockIdx.x + (long long)k * NBLK_B;
        if (t >= NTILES) break;
        asm volatile("cp.async.wait_group 2;");      // oldest stage landed (this thread)
        __syncthreads();                             // ... and for every thread
        const char*  st = smem + OFF_STAGE + (((unsigned)k) & (NS - 1)) * STAGE_STRIDE;
        const float* sv = (const float*)(st + TILE * 8);
        const unsigned* si = (const unsigned*)st;
        if (is64) {
            #pragma unroll
            for (int r = 0; r < 4; ++r) {
                const int e = wbase + r * 32;
                hist_step(si[2 * e], sv[e], lane, mlt, s_pos, myhist);  // low word
            }
        } else {
            #pragma unroll
            for (int r = 0; r < 4; ++r) {
                const int e = wbase + r * 32;
                hist_step(si[e], sv[e], lane, mlt, s_pos, myhist);
            }
        }
        __syncthreads();                             // all warps done reading stage
        issue(k + NS - 1);                           // refill the freed buffer
    }
    __syncthreads();

    // Combine 8 warp histograms; one u32 partial per bin per block.
    for (int k = tid; k < kNumPos; k += THR_B) {
        unsigned c = 0;
        #pragma unroll
        for (int w = 0; w < NWARP_B; ++w) c += s_hist[(size_t)w * kNumPos + k];
        g_partial[(size_t)blockIdx.x * kNumPos + k] = c;
    }
}

// ---------------------------------------------------------------------------
// Pass C: 256 blocks x 256 threads. out layout: [mrr, sample_mrr[8192]]
// ---------------------------------------------------------------------------
__global__ void __launch_bounds__(256) finalize_kernel(float* __restrict__ out) {
    const int tid   = threadIdx.x;
    const int bsub  = tid & 31;
    const int chunk = tid >> 5;
    const int bin   = blockIdx.x * 32 + bsub;

    unsigned c = 0;
    #pragma unroll
    for (int b = chunk; b < NBLK_B; b += 8)
        c += g_partial[(size_t)b * kNumPos + bin];

    __shared__ unsigned sc[256];
    sc[tid] = c;
    __syncthreads();

    if (chunk == 0) {
        unsigned tot = c;
        #pragma unroll
        for (int w = 1; w < 8; ++w) tot += sc[w * 32 + bsub];
        const float mrr_i = 1.0f / (float)(1u + tot);
        out[1 + bin] = mrr_i;

        float s = mrr_i;
        #pragma unroll
        for (int o = 16; o; o >>= 1) s += __shfl_down_sync(0xffffffffu, s, o);
        if (bsub == 0) atomicAdd(out, s * (1.0f / (float)kNumPos));
    }
}

// ---------------------------------------------------------------------------
extern "C" void kernel_launch(void* const* d_in, const int* in_sizes, int n_in,
                              void* d_out, int out_size) {
    const float* pred = (const float*)d_in[0];
    const void*  idx  = (const void*)d_in[1];
    float*       out  = (float*)d_out;

    cudaFuncSetAttribute(count_kernel, cudaFuncAttributeMaxDynamicSharedMemorySize, SMEM_B);

    detect_kernel<<<1, 32>>>((const unsigned long long*)idx);
    scatter_pos_kernel<<<2048, 256>>>(idx, pred, out);
    count_kernel<<<NBLK_B, THR_B, SMEM_B>>>(idx, pred);
    finalize_kernel<<<kNumPos / 32, 256>>>(out);
}

// round 5
// speedup vs baseline: 1.4820x; 1.1534x over previous
#include <cuda_runtime.h>
#include <cstdint>

// Problem constants (fixed shapes for this problem instance).
static constexpr int       kNumPos = 8192;
static constexpr long long kNTot   = 32776192LL;   // 8192 + 8192*4000

// Count-kernel geometry: one wave of 152 CTAs, 8 warps each.
static constexpr int NBLK_B  = 152;
static constexpr int THR_B   = 256;
static constexpr int NWARP_B = 8;
static constexpr int SMEM_B  = kNumPos * 4 + NWARP_B * kNumPos * 2;  // 160 KB

static constexpr int NBLK_A  = 2048;  // scatter grid

__device__ float    g_pos[kNumPos];
__device__ unsigned g_partial[NBLK_B * kNumPos];
__device__ int      g_is64;

// ---------------------------------------------------------------------------
__global__ void detect_kernel(const unsigned long long* __restrict__ idx) {
    if (threadIdx.x == 0 && blockIdx.x == 0) {
        int is64 = 1;
        #pragma unroll
        for (int i = 0; i < 64; ++i)
            if (idx[i] >= (unsigned long long)kNTot) is64 = 0;
        g_is64 = is64;
    }
}

// ---------------------------------------------------------------------------
// Pass A: scan index, scatter pos values. Loads are explicitly front-batched
// into registers BEFORE any conditional store, so the (possible-alias) stores
// to g_pos cannot serialize the load stream.
// ---------------------------------------------------------------------------
__global__ void __launch_bounds__(256) scatter_pos_kernel(
    const void* __restrict__ idx_raw, const float* __restrict__ pred,
    float* __restrict__ out) {
    if (blockIdx.x == 0 && threadIdx.x == 0) out[0] = 0.0f;
    const long long base   = blockIdx.x * 256LL + threadIdx.x;
    const long long stride = (long long)NBLK_A * 256LL;
    constexpr int U = 8;
    const long long bigstride = stride * U;

    if (g_is64) {
        const ulonglong2* idx2 = (const ulonglong2*)idx_raw;   // 2 int64 / load
        const long long nvec = kNTot / 2;
        const long long nmax = nvec - 1;
        const int iters = (int)((nvec + bigstride - 1) / bigstride);
        #pragma unroll 1
        for (int it = 0; it < iters; ++it) {
            ulonglong2 iv[U];
            // ---- load phase: 8 independent 16B LDGs, no stores in between ----
            #pragma unroll
            for (int u = 0; u < U; ++u) {
                long long v = base + (long long)it * bigstride + (long long)u * stride;
                iv[u] = idx2[v > nmax ? nmax : v];
            }
            // ---- process phase: rare conditional gathers + stores ----
            #pragma unroll
            for (int u = 0; u < U; ++u) {
                long long v = base + (long long)it * bigstride + (long long)u * stride;
                if (v < nvec) {
                    if (iv[u].x < (unsigned long long)kNumPos) g_pos[iv[u].x] = pred[2 * v];
                    if (iv[u].y < (unsigned long long)kNumPos) g_pos[iv[u].y] = pred[2 * v + 1];
                }
            }
        }
    } else {
        const uint4* idx4 = (const uint4*)idx_raw;             // 4 int32 / load
        const long long nvec = kNTot / 4;
        const long long nmax = nvec - 1;
        const int iters = (int)((nvec + bigstride - 1) / bigstride);
        #pragma unroll 1
        for (int it = 0; it < iters; ++it) {
            uint4 iv[U];
            #pragma unroll
            for (int u = 0; u < U; ++u) {
                long long v = base + (long long)it * bigstride + (long long)u * stride;
                iv[u] = idx4[v > nmax ? nmax : v];
            }
            #pragma unroll
            for (int u = 0; u < U; ++u) {
                long long v = base + (long long)it * bigstride + (long long)u * stride;
                if (v < nvec) {
                    const long long e = 4 * v;
                    if (iv[u].x < (unsigned)kNumPos) g_pos[iv[u].x] = pred[e];
                    if (iv[u].y < (unsigned)kNumPos) g_pos[iv[u].y] = pred[e + 1];
                    if (iv[u].z < (unsigned)kNumPos) g_pos[iv[u].z] = pred[e + 2];
                    if (iv[u].w < (unsigned)kNumPos) g_pos[iv[u].w] = pred[e + 3];
                }
            }
        }
    }
}

// ---------------------------------------------------------------------------
// Pass B (verbatim Round-2, the 284.9us composite): per-warp u16 smem
// histograms; __match_any_sync leader aggregation. u16 safe: bin count <= 4000.
// ---------------------------------------------------------------------------
__device__ __forceinline__ void hist_step(unsigned long long i, float val, int lane,
                                          const float* __restrict__ s_pos,
                                          unsigned short* __restrict__ myhist) {
    const bool neg = (i >= (unsigned long long)kNumPos);
    const unsigned s = neg ? (unsigned)(i - (unsigned long long)kNumPos) / 4000u : 0u;
    const float p = s_pos[s];                       // safe: s==0 for non-neg lanes
    const bool bit = neg && (val > p);
    const unsigned key = bit ? s : (unsigned)(kNumPos + lane);
    const unsigned grp = __match_any_sync(0xffffffffu, key);
    if (bit && lane == (__ffs(grp) - 1)) {
        myhist[s] = (unsigned short)(myhist[s] + (unsigned)__popc(grp));
    }
}

__global__ void __launch_bounds__(THR_B, 1) count_kernel(
    const void* __restrict__ idx_raw, const float* __restrict__ pred) {
    extern __shared__ unsigned char smem_raw[];
    float*          s_pos  = (float*)smem_raw;
    unsigned short* s_hist = (unsigned short*)(smem_raw + (size_t)kNumPos * 4);
    const int tid  = threadIdx.x;
    const int lane = tid & 31;
    unsigned short* myhist = s_hist + (size_t)(tid >> 5) * kNumPos;

    for (int k = tid; k < kNumPos; k += THR_B) s_pos[k] = g_pos[k];
    unsigned* s_hist32 = (unsigned*)s_hist;
    for (int k = tid; k < NWARP_B * kNumPos / 2; k += THR_B) s_hist32[k] = 0u;
    __syncthreads();

    if (g_is64) {
        constexpr int U = 8;                           // 16 elements/thread/stage
        const ulonglong2* idx2 = (const ulonglong2*)idx_raw;
        const float2*     val2 = (const float2*)pred;
        const long long nvec      = kNTot / 2;
        const long long stride    = (long long)NBLK_B * THR_B;
        const long long bigstride = stride * U;
        const long long base      = blockIdx.x * (long long)THR_B + tid;
        const int iters = (int)((nvec + bigstride - 1) / bigstride);
        for (int it = 0; it < iters; ++it) {
            ulonglong2 iv[U];
            float2     vv[U];
            #pragma unroll
            for (int u = 0; u < U; ++u) {
                const long long v = base + (long long)it * bigstride + (long long)u * stride;
                iv[u] = make_ulonglong2(0ull, 0ull);
                vv[u] = make_float2(0.f, 0.f);
                if (v < nvec) { iv[u] = idx2[v]; vv[u] = val2[v]; }
            }
            #pragma unroll
            for (int u = 0; u < U; ++u) {
                hist_step(iv[u].x, vv[u].x, lane, s_pos, myhist);
                hist_step(iv[u].y, vv[u].y, lane, s_pos, myhist);
            }
        }
    } else {
        constexpr int U = 8;                           // 32 elements/thread/stage
        const uint4*  idx4 = (const uint4*)idx_raw;
        const float4* val4 = (const float4*)pred;
        const long long nvec      = kNTot / 4;
        const long long stride    = (long long)NBLK_B * THR_B;
        const long long bigstride = stride * U;
        const long long base      = blockIdx.x * (long long)THR_B + tid;
        const int iters = (int)((nvec + bigstride - 1) / bigstride);
        for (int it = 0; it < iters; ++it) {
            uint4  iv[U];
            float4 vv[U];
            #pragma unroll
            for (int u = 0; u < U; ++u) {
                const long long v = base + (long long)it * bigstride + (long long)u * stride;
                iv[u] = make_uint4(0u, 0u, 0u, 0u);
                vv[u] = make_float4(0.f, 0.f, 0.f, 0.f);
                if (v < nvec) { iv[u] = idx4[v]; vv[u] = val4[v]; }
            }
            #pragma unroll
            for (int u = 0; u < U; ++u) {
                hist_step(iv[u].x, vv[u].x, lane, s_pos, myhist);
                hist_step(iv[u].y, vv[u].y, lane, s_pos, myhist);
                hist_step(iv[u].z, vv[u].z, lane, s_pos, myhist);
                hist_step(iv[u].w, vv[u].w, lane, s_pos, myhist);
            }
        }
    }
    __syncthreads();

    for (int k = tid; k < kNumPos; k += THR_B) {
        unsigned c = 0;
        #pragma unroll
        for (int w = 0; w < NWARP_B; ++w) c += s_hist[(size_t)w * kNumPos + k];
        g_partial[(size_t)blockIdx.x * kNumPos + k] = c;
    }
}

// ---------------------------------------------------------------------------
// Pass C: 256 blocks x 256 threads. out layout: [mrr, sample_mrr[8192]]
// ---------------------------------------------------------------------------
__global__ void __launch_bounds__(256) finalize_kernel(float* __restrict__ out) {
    const int tid   = threadIdx.x;
    const int bsub  = tid & 31;
    const int chunk = tid >> 5;
    const int bin   = blockIdx.x * 32 + bsub;

    unsigned c = 0;
    #pragma unroll
    for (int b = chunk; b < NBLK_B; b += 8)
        c += g_partial[(size_t)b * kNumPos + bin];

    __shared__ unsigned sc[256];
    sc[tid] = c;
    __syncthreads();

    if (chunk == 0) {
        unsigned tot = c;
        #pragma unroll
        for (int w = 1; w < 8; ++w) tot += sc[w * 32 + bsub];
        const float mrr_i = 1.0f / (float)(1u + tot);
        out[1 + bin] = mrr_i;

        float s = mrr_i;
        #pragma unroll
        for (int o = 16; o; o >>= 1) s += __shfl_down_sync(0xffffffffu, s, o);
        if (bsub == 0) atomicAdd(out, s * (1.0f / (float)kNumPos));
    }
}

// ---------------------------------------------------------------------------
extern "C" void kernel_launch(void* const* d_in, const int* in_sizes, int n_in,
                              void* d_out, int out_size) {
    const float* pred = (const float*)d_in[0];
    const void*  idx  = (const void*)d_in[1];
    float*       out  = (float*)d_out;

    cudaFuncSetAttribute(count_kernel, cudaFuncAttributeMaxDynamicSharedMemorySize, SMEM_B);

    detect_kernel<<<1, 32>>>((const unsigned long long*)idx);
    scatter_pos_kernel<<<NBLK_A, 256>>>(idx, pred, out);
    count_kernel<<<NBLK_B, THR_B, SMEM_B>>>(idx, pred);
    finalize_kernel<<<kNumPos / 32, 256>>>(out);
}

// round 6
// speedup vs baseline: 1.6064x; 1.0839x over previous
#include <cuda_runtime.h>
#include <cstdint>

// Problem constants (fixed shapes for this problem instance).
static constexpr int       kNumPos = 8192;
static constexpr long long kNTot   = 32776192LL;            // 8192 + 8192*4000
static constexpr long long kMagicM = 34359739LL;            // ceil(2^37/4000)
static constexpr long long kMagicB = -281474981888LL;       // -8192*M
static constexpr int       kShift  = 37;

// Count-kernel geometry: one wave of 152 CTAs, 12 warps each.
static constexpr int NBLK_B  = 152;
static constexpr int THR_B   = 384;
static constexpr int NWARP_B = 12;
static constexpr int SMEM_B  = kNumPos * 4 + NWARP_B * kNumPos * 2;  // 224 KB

static constexpr int NBLK_A  = 2048;  // scatter grid

__device__ float    g_pos[kNumPos];
__device__ unsigned g_partial[NBLK_B * kNumPos];
__device__ int      g_is64;

// ---------------------------------------------------------------------------
__global__ void detect_kernel(const unsigned long long* __restrict__ idx) {
    if (threadIdx.x == 0 && blockIdx.x == 0) {
        int is64 = 1;
        #pragma unroll
        for (int i = 0; i < 64; ++i)
            if (idx[i] >= (unsigned long long)kNTot) is64 = 0;
        g_is64 = is64;
    }
}

// ---------------------------------------------------------------------------
// Pass A: scan index, scatter pos values. Front-batched loads before the
// conditional (possibly aliasing) stores. (Round-5 version, measured good.)
// ---------------------------------------------------------------------------
__global__ void __launch_bounds__(256) scatter_pos_kernel(
    const void* __restrict__ idx_raw, const float* __restrict__ pred,
    float* __restrict__ out) {
    if (blockIdx.x == 0 && threadIdx.x == 0) out[0] = 0.0f;
    const long long base   = blockIdx.x * 256LL + threadIdx.x;
    const long long stride = (long long)NBLK_A * 256LL;
    constexpr int U = 8;
    const long long bigstride = stride * U;

    if (g_is64) {
        const ulonglong2* idx2 = (const ulonglong2*)idx_raw;
        const long long nvec = kNTot / 2;
        const long long nmax = nvec - 1;
        const int iters = (int)((nvec + bigstride - 1) / bigstride);
        #pragma unroll 1
        for (int it = 0; it < iters; ++it) {
            ulonglong2 iv[U];
            #pragma unroll
            for (int u = 0; u < U; ++u) {
                long long v = base + (long long)it * bigstride + (long long)u * stride;
                iv[u] = idx2[v > nmax ? nmax : v];
            }
            #pragma unroll
            for (int u = 0; u < U; ++u) {
                long long v = base + (long long)it * bigstride + (long long)u * stride;
                if (v < nvec) {
                    if (iv[u].x < (unsigned long long)kNumPos) g_pos[iv[u].x] = pred[2 * v];
                    if (iv[u].y < (unsigned long long)kNumPos) g_pos[iv[u].y] = pred[2 * v + 1];
                }
            }
        }
    } else {
        const uint4* idx4 = (const uint4*)idx_raw;
        const long long nvec = kNTot / 4;
        const long long nmax = nvec - 1;
        const int iters = (int)((nvec + bigstride - 1) / bigstride);
        #pragma unroll 1
        for (int it = 0; it < iters; ++it) {
            uint4 iv[U];
            #pragma unroll
            for (int u = 0; u < U; ++u) {
                long long v = base + (long long)it * bigstride + (long long)u * stride;
                iv[u] = idx4[v > nmax ? nmax : v];
            }
            #pragma unroll
            for (int u = 0; u < U; ++u) {
                long long v = base + (long long)it * bigstride + (long long)u * stride;
                if (v < nvec) {
                    const long long e = 4 * v;
                    if (iv[u].x < (unsigned)kNumPos) g_pos[iv[u].x] = pred[e];
                    if (iv[u].y < (unsigned)kNumPos) g_pos[iv[u].y] = pred[e + 1];
                    if (iv[u].z < (unsigned)kNumPos) g_pos[iv[u].z] = pred[e + 2];
                    if (iv[u].w < (unsigned)kNumPos) g_pos[iv[u].w] = pred[e + 3];
                }
            }
        }
    }
}

// ---------------------------------------------------------------------------
// Pass B: per-warp u16 smem histograms (12 warps), match-based leader
// aggregation, magic-divide bin computation (exact for i < 2^25).
// ---------------------------------------------------------------------------
__device__ __forceinline__ void hist_step(unsigned i, float val, int lane,
                                          unsigned mlt,
                                          const float* __restrict__ s_pos,
                                          unsigned short* __restrict__ myhist) {
    // s = (i - 8192) / 4000; pos elements (i<8192) wrap to huge s -> bit false.
    const unsigned s  = (unsigned)(((long long)i * kMagicM + kMagicB) >> kShift);
    const unsigned sm = s & 8191u;
    const float    p  = s_pos[sm];                  // masked -> always-safe addr
    const bool bit = (s < 8192u) && (val > p);
    const unsigned key = bit ? sm : 8192u + (unsigned)lane;
    const unsigned grp = __match_any_sync(0xffffffffu, key);
    if (bit && (grp & mlt) == 0u) {                 // leader = lowest lane in group
        myhist[sm] = (unsigned short)(myhist[sm] + (unsigned)__popc(grp));
    }
}

__global__ void __launch_bounds__(THR_B, 1) count_kernel(
    const void* __restrict__ idx_raw, const float* __restrict__ pred) {
    extern __shared__ unsigned char smem_raw[];
    float*          s_pos  = (float*)smem_raw;
    unsigned short* s_hist = (unsigned short*)(smem_raw + (size_t)kNumPos * 4);
    const int tid  = threadIdx.x;
    const int lane = tid & 31;
    unsigned mlt;
    asm("mov.u32 %0, %%lanemask_lt;" : "=r"(mlt));
    unsigned short* myhist = s_hist + (size_t)(tid >> 5) * kNumPos;

    for (int k = tid; k < kNumPos; k += THR_B) s_pos[k] = g_pos[k];
    unsigned* s_hist32 = (unsigned*)s_hist;
    for (int k = tid; k < NWARP_B * kNumPos / 2; k += THR_B) s_hist32[k] = 0u;
    __syncthreads();

    constexpr int U = 4;   // small batch: fewer live regs -> deeper interleave
    if (g_is64) {
        const ulonglong2* idx2 = (const ulonglong2*)idx_raw;
        const float2*     val2 = (const float2*)pred;
        const long long nvec      = kNTot / 2;
        const long long stride    = (long long)NBLK_B * THR_B;
        const long long bigstride = stride * U;
        const long long base      = blockIdx.x * (long long)THR_B + tid;
        const int iters = (int)((nvec + bigstride - 1) / bigstride);
        for (int it = 0; it < iters; ++it) {
            ulonglong2 iv[U];
            float2     vv[U];
            #pragma unroll
            for (int u = 0; u < U; ++u) {
                const long long v = base + (long long)it * bigstride + (long long)u * stride;
                iv[u] = make_ulonglong2(~0ull, ~0ull);   // OOB -> bit false
                vv[u] = make_float2(0.f, 0.f);
                if (v < nvec) { iv[u] = idx2[v]; vv[u] = val2[v]; }
            }
            #pragma unroll
            for (int u = 0; u < U; ++u) {
                hist_step((unsigned)iv[u].x, vv[u].x, lane, mlt, s_pos, myhist);
                hist_step((unsigned)iv[u].y, vv[u].y, lane, mlt, s_pos, myhist);
            }
        }
    } else {
        const uint4*  idx4 = (const uint4*)idx_raw;
        const float4* val4 = (const float4*)pred;
        const long long nvec      = kNTot / 4;
        const long long stride    = (long long)NBLK_B * THR_B;
        const long long bigstride = stride * U;
        const long long base      = blockIdx.x * (long long)THR_B + tid;
        const int iters = (int)((nvec + bigstride - 1) / bigstride);
        for (int it = 0; it < iters; ++it) {
            uint4  iv[U];
            float4 vv[U];
            #pragma unroll
            for (int u = 0; u < U; ++u) {
                const long long v = base + (long long)it * bigstride + (long long)u * stride;
                iv[u] = make_uint4(~0u, ~0u, ~0u, ~0u);  // OOB -> bit false
                vv[u] = make_float4(0.f, 0.f, 0.f, 0.f);
                if (v < nvec) { iv[u] = idx4[v]; vv[u] = val4[v]; }
            }
            #pragma unroll
            for (int u = 0; u < U; ++u) {
                hist_step(iv[u].x, vv[u].x, lane, mlt, s_pos, myhist);
                hist_step(iv[u].y, vv[u].y, lane, mlt, s_pos, myhist);
                hist_step(iv[u].z, vv[u].z, lane, mlt, s_pos, myhist);
                hist_step(iv[u].w, vv[u].w, lane, mlt, s_pos, myhist);
            }
        }
    }
    __syncthreads();

    // Combine 12 warp histograms; one u32 partial per bin per block.
    for (int k = tid; k < kNumPos; k += THR_B) {
        unsigned c = 0;
        #pragma unroll
        for (int w = 0; w < NWARP_B; ++w) c += s_hist[(size_t)w * kNumPos + k];
        g_partial[(size_t)blockIdx.x * kNumPos + k] = c;
    }
}

// ---------------------------------------------------------------------------
// Pass C: 256 blocks x 256 threads. out layout: [mrr, sample_mrr[8192]]
// ---------------------------------------------------------------------------
__global__ void __launch_bounds__(256) finalize_kernel(float* __restrict__ out) {
    const int tid   = threadIdx.x;
    const int bsub  = tid & 31;
    const int chunk = tid >> 5;
    const int bin   = blockIdx.x * 32 + bsub;

    unsigned c = 0;
    #pragma unroll
    for (int b = chunk; b < NBLK_B; b += 8)
        c += g_partial[(size_t)b * kNumPos + bin];

    __shared__ unsigned sc[256];
    sc[tid] = c;
    __syncthreads();

    if (chunk == 0) {
        unsigned tot = c;
        #pragma unroll
        for (int w = 1; w < 8; ++w) tot += sc[w * 32 + bsub];
        const float mrr_i = 1.0f / (float)(1u + tot);
        out[1 + bin] = mrr_i;

        float s = mrr_i;
        #pragma unroll
        for (int o = 16; o; o >>= 1) s += __shfl_down_sync(0xffffffffu, s, o);
        if (bsub == 0) atomicAdd(out, s * (1.0f / (float)kNumPos));
    }
}

// ---------------------------------------------------------------------------
extern "C" void kernel_launch(void* const* d_in, const int* in_sizes, int n_in,
                              void* d_out, int out_size) {
    const float* pred = (const float*)d_in[0];
    const void*  idx  = (const void*)d_in[1];
    float*       out  = (float*)d_out;

    cudaFuncSetAttribute(count_kernel, cudaFuncAttributeMaxDynamicSharedMemorySize, SMEM_B);

    detect_kernel<<<1, 32>>>((const unsigned long long*)idx);
    scatter_pos_kernel<<<NBLK_A, 256>>>(idx, pred, out);
    count_kernel<<<NBLK_B, THR_B, SMEM_B>>>(idx, pred);
    finalize_kernel<<<kNumPos / 32, 256>>>(out);
}